// round 4
// baseline (speedup 1.0000x reference)
#include <cuda_runtime.h>
#include <cstdint>

// Problem constants
#define NN    4096
#define RR    4
#define LL    8
#define HH    64
#define CC    16
#define FF    64
#define FEAT  144            // FF + HH + CC
#define NPAIR (RR*NN)        // 16384

// Device scratch (static globals: no runtime allocation)
__device__ float g_lg[(size_t)NN * NN];   // log(prob + 1e-9), 64 MB (L2-resident)
__device__ int   g_walk[LL][NPAIR];       // un-flipped walk nodes: [t][r*N+n]

// ---------------------------------------------------------------------------
// Threefry-2x32, 20 rounds — canonical, matches JAX's threefry2x32 primitive
// ---------------------------------------------------------------------------
__device__ __forceinline__ void d_threefry(uint32_t k1, uint32_t k2,
                                           uint32_t& x0, uint32_t& x1) {
  uint32_t k3 = k1 ^ k2 ^ 0x1BD11BDAu;
  x0 += k1; x1 += k2;
#define TFR(r) { x0 += x1; x1 = __funnelshift_l(x1, x1, (r)); x1 ^= x0; }
  TFR(13) TFR(15) TFR(26) TFR(6)
  x0 += k2; x1 += k3 + 1u;
  TFR(17) TFR(29) TFR(16) TFR(24)
  x0 += k3; x1 += k1 + 2u;
  TFR(13) TFR(15) TFR(26) TFR(6)
  x0 += k1; x1 += k2 + 3u;
  TFR(17) TFR(29) TFR(16) TFR(24)
  x0 += k2; x1 += k3 + 4u;
  TFR(13) TFR(15) TFR(26) TFR(6)
  x0 += k3; x1 += k1 + 5u;
#undef TFR
}

static void host_threefry(uint32_t k1, uint32_t k2, uint32_t& x0, uint32_t& x1) {
  uint32_t k3 = k1 ^ k2 ^ 0x1BD11BDAu;
  x0 += k1; x1 += k2;
#define TFRH(r) { x0 += x1; x1 = (x1 << (r)) | (x1 >> (32 - (r))); x1 ^= x0; }
  TFRH(13) TFRH(15) TFRH(26) TFRH(6)
  x0 += k2; x1 += k3 + 1u;
  TFRH(17) TFRH(29) TFRH(16) TFRH(24)
  x0 += k3; x1 += k1 + 2u;
  TFRH(13) TFRH(15) TFRH(26) TFRH(6)
  x0 += k1; x1 += k2 + 3u;
  TFRH(17) TFRH(29) TFRH(16) TFRH(24)
  x0 += k2; x1 += k3 + 4u;
  TFRH(13) TFRH(15) TFRH(26) TFRH(6)
  x0 += k3; x1 += k1 + 5u;
#undef TFRH
}

__device__ __forceinline__ float sigmoidf(float x) {
  if (x >= 0.f) { float z = expf(-x); return 1.f / (1.f + z); }
  float z = expf(x); return z / (1.f + z);
}

// ---------------------------------------------------------------------------
// Phase 0: log-prob table
// ---------------------------------------------------------------------------
__global__ void __launch_bounds__(256) lg_kernel(const float* __restrict__ p) {
  size_t i      = (size_t)blockIdx.x * 256 + threadIdx.x;
  size_t stride = (size_t)gridDim.x * 256;
  const size_t total = (size_t)NN * NN;
  for (; i < total; i += stride)
    g_lg[i] = logf(p[i] + 1e-9f);
}

__global__ void init_walk_kernel() {
  int p = blockIdx.x * 256 + threadIdx.x;
  if (p < NPAIR) g_walk[0][p] = p & (NN - 1);
}

// ---------------------------------------------------------------------------
// Phase 1: one Gumbel-max categorical step. One block per (r,n) pair.
// Bit-exact replication of:
//   bits = tf2x32(key, (0, i)).x0 ^ .x1 ;  i = (r*N+n)*N + j   (row-major)
//   f = bitcast((bits>>9)|0x3f800000)-1 ;  u = max(tiny, f)
//   v = lg[cur, j] + (-log(-log(u)))   ;  argmax_j, first index on ties
// ---------------------------------------------------------------------------
__global__ void __launch_bounds__(256) walk_step_kernel(int t, uint32_t k1, uint32_t k2) {
  int p   = blockIdx.x;                    // r*N + n
  int cur = g_walk[t - 1][p];
  const float* __restrict__ row = g_lg + (size_t)cur * NN;
  uint32_t base = (uint32_t)p * (uint32_t)NN;

  float bv = __int_as_float(0xff800000);   // -inf
  int   bj = 0;
#pragma unroll
  for (int it = 0; it < NN / 256; it++) {
    int j = threadIdx.x + it * 256;
    uint32_t x0 = 0u, x1 = base + (uint32_t)j;   // counter hi=0, lo=i (i < 2^26)
    d_threefry(k1, k2, x0, x1);
    uint32_t bits = x0 ^ x1;
    float f = __uint_as_float((bits >> 9) | 0x3f800000u) - 1.0f;
    float u = fmaxf(1.17549435e-38f, f);
    float g = -logf(-logf(u));
    float v = __ldg(row + j) + g;
    if (v > bv) { bv = v; bj = j; }        // strict > keeps earliest j
  }

  // warp reduce (min index on equal value)
  for (int off = 16; off; off >>= 1) {
    float ov = __shfl_down_sync(0xffffffffu, bv, off);
    int   oj = __shfl_down_sync(0xffffffffu, bj, off);
    if (ov > bv || (ov == bv && oj < bj)) { bv = ov; bj = oj; }
  }
  __shared__ float sv[8];
  __shared__ int   sj[8];
  int wid = threadIdx.x >> 5;
  if ((threadIdx.x & 31) == 0) { sv[wid] = bv; sj[wid] = bj; }
  __syncthreads();
  if (threadIdx.x == 0) {
    bv = sv[0]; bj = sj[0];
    for (int w = 1; w < 8; w++)
      if (sv[w] > bv || (sv[w] == bv && sj[w] < bj)) { bv = sv[w]; bj = sj[w]; }
    g_walk[t][p] = bj;
  }
}

// ---------------------------------------------------------------------------
// Phase 2: trajectory recurrence. One warp per (r,n); 8 warps per block.
// Full fp32 GEMVs (matches XLA's fused fp32 scan body).
// ---------------------------------------------------------------------------
__global__ void __launch_bounds__(256) rye_kernel(
    const float* __restrict__ inv_in, const float* __restrict__ eq_in,
    const float* __restrict__ W1, const float* __restrict__ b1,
    const float* __restrict__ W2, const float* __restrict__ b2,
    float* __restrict__ out) {
  __shared__ float sW1[FEAT * HH];       // 36864 B
  __shared__ float sW2[HH * 2 * CC];     // 8192 B
  __shared__ float sb1[HH];
  __shared__ float sb2[2 * CC];
  __shared__ float sfeat[8][FEAT];       // features per warp
  __shared__ float seqh[8][3 * CC];      // eq hidden state
  __shared__ float scoef[8][2 * CC];
  __shared__ float seqin[8][4];          // eq_diff (3 used)

  int tid = threadIdx.x;
  for (int i = tid; i < FEAT * HH; i += 256) sW1[i] = W1[i];
  for (int i = tid; i < HH * 2 * CC; i += 256) sW2[i] = W2[i];
  if (tid < HH)     sb1[tid] = b1[tid];
  if (tid < 2 * CC) sb2[tid] = b2[tid];

  int w    = tid >> 5;
  int lane = tid & 31;
  int pair = blockIdx.x * 8 + w;
  int r    = pair >> 12;
  int n    = pair & (NN - 1);

  // init state: inv_h = 0, eq_h = 0
  sfeat[w][FF + lane]      = 0.f;
  sfeat[w][FF + 32 + lane] = 0.f;
  if (lane < 16) {
    seqh[w][lane] = 0.f; seqh[w][16 + lane] = 0.f; seqh[w][32 + lane] = 0.f;
  }
  __syncthreads();

  const size_t EQ_BASE = (size_t)RR * LL * NN * HH;   // 8388608

  for (int l = 0; l < LL; l++) {
    int node = g_walk[LL - 1 - l][pair];
    // invariant features
    sfeat[w][lane]      = __ldg(inv_in + (size_t)node * FF + lane);
    sfeat[w][32 + lane] = __ldg(inv_in + (size_t)node * FF + 32 + lane);
    // equivariant step input
    if (lane < 3) {
      float e = 0.f;
      if (l > 0) {
        int prev = g_walk[LL - l][pair];
        e = __ldg(eq_in + (size_t)node * 3 + lane) - __ldg(eq_in + (size_t)prev * 3 + lane);
      }
      seqin[w][lane] = e;
    }
    // squared norms of eq_h channels
    if (lane < 16) {
      float d0 = seqh[w][lane], d1 = seqh[w][16 + lane], d2 = seqh[w][32 + lane];
      sfeat[w][FF + HH + lane] = d0 * d0 + d1 * d1 + d2 * d2;
    }
    __syncwarp();

    // GEMV1: inv_h_new = tanh(feats @ W1 + b1); lane does h=lane, h+32
    float a0 = 0.f, a1 = 0.f;
#pragma unroll 4
    for (int k = 0; k < FEAT; k++) {
      float fk = sfeat[w][k];
      a0 = fmaf(fk, sW1[k * HH + lane], a0);
      a1 = fmaf(fk, sW1[k * HH + 32 + lane], a1);
    }
    float h0 = tanhf(a0 + sb1[lane]);
    float h1 = tanhf(a1 + sb1[32 + lane]);
    __syncwarp();
    sfeat[w][FF + lane]      = h0;       // inv_h for GEMV2 + next step
    sfeat[w][FF + 32 + lane] = h1;
    __syncwarp();

    // GEMV2: coef = inv_h_new @ W2 + b2; lane computes output `lane` (of 32)
    float acc = 0.f;
#pragma unroll 8
    for (int k = 0; k < HH; k++)
      acc = fmaf(sfeat[w][FF + k], sW2[k * (2 * CC) + lane], acc);
    scoef[w][lane] = acc + sb2[lane];
    __syncwarp();

    // outputs + eq update
    size_t inv_off = (((size_t)r * LL + l) * NN + n) * HH;
    out[inv_off + lane]      = h0;
    out[inv_off + 32 + lane] = h1;
    if (lane < 16) {
      float gate = sigmoidf(scoef[w][lane]);
      float scl  = scoef[w][CC + lane];
      size_t eq_off = EQ_BASE + (((size_t)r * LL + l) * NN + n) * (3 * CC) + lane;
      float e0 = seqin[w][0], e1 = seqin[w][1], e2 = seqin[w][2];
      float v0 = seqh[w][lane]      * gate + e0 * scl;
      float v1 = seqh[w][16 + lane] * gate + e1 * scl;
      float v2 = seqh[w][32 + lane] * gate + e2 * scl;
      seqh[w][lane] = v0; seqh[w][16 + lane] = v1; seqh[w][32 + lane] = v2;
      out[eq_off]           = v0;
      out[eq_off + CC]      = v1;
      out[eq_off + 2 * CC]  = v2;
    }
    __syncwarp();
  }
}

// ---------------------------------------------------------------------------
extern "C" void kernel_launch(void* const* d_in, const int* in_sizes, int n_in,
                              void* d_out, int out_size) {
  const float* prob = (const float*)d_in[0];
  const float* inv  = (const float*)d_in[1];
  const float* eq   = (const float*)d_in[2];
  const float* W1   = (const float*)d_in[3];
  const float* b1   = (const float*)d_in[4];
  const float* W2   = (const float*)d_in[5];
  const float* b2   = (const float*)d_in[6];
  float* out = (float*)d_out;
  (void)in_sizes; (void)n_in; (void)out_size;

  lg_kernel<<<8192, 256>>>(prob);
  init_walk_kernel<<<NPAIR / 256, 256>>>();

  // Step keys: jax.random.split(key(42), 7) fold-like:
  //   subkey[t] = threefry2x32((0,42), (0, t))
  for (int t = 1; t < LL; t++) {
    uint32_t x0 = 0u, x1 = (uint32_t)(t - 1);
    host_threefry(0u, 42u, x0, x1);
    walk_step_kernel<<<NPAIR, 256>>>(t, x0, x1);
  }

  rye_kernel<<<NPAIR / 8, 256>>>(inv, eq, W1, b1, W2, b2, out);
}

// round 5
// speedup vs baseline: 1.0634x; 1.0634x over previous
#include <cuda_runtime.h>
#include <cstdint>

// Problem constants
#define NN    4096
#define RR    4
#define LL    8
#define HH    64
#define CC    16
#define FF    64
#define FEAT  144            // FF + HH + CC
#define NPAIR (RR*NN)        // 16384

// Device scratch (static data: no runtime allocation)
__device__ int      g_walk[LL][NPAIR];    // un-flipped walk nodes: [t][r*N+n]
__device__ uint32_t g_rotm[4] = {1u << 13, 1u << 15, 1u << 17, 1u << 29};

// ---------------------------------------------------------------------------
// Threefry-2x32, 20 rounds — canonical, matches JAX's threefry2x32 primitive.
// RS: shift-form rotation (SHF, ALU pipe).
// RW: wide-multiply rotation (IMAD.WIDE, FMA pipe) — multiplier comes from a
//     runtime register so ptxas cannot strength-reduce it back to shifts.
// Both produce identical bits.
// ---------------------------------------------------------------------------
#define RS(r) { x0 += x1; x1 = __funnelshift_l(x1, x1, (r)) ^ x0; }
#define RW(m) { x0 += x1; unsigned long long tt = (unsigned long long)x1 * (m); \
                x1 = ((uint32_t)tt | (uint32_t)(tt >> 32)) ^ x0; }

__device__ __forceinline__ uint32_t tf_wide(uint32_t ctr,
                                            uint32_t k1, uint32_t k2, uint32_t k3,
                                            uint32_t m13, uint32_t m15,
                                            uint32_t m17, uint32_t m29) {
  uint32_t x0 = k1, x1 = ctr + k2;
  RW(m13) RW(m15) RS(26) RS(6)
  x0 += k2; x1 += k3 + 1u;
  RW(m17) RW(m29) RS(16) RS(24)
  x0 += k3; x1 += k1 + 2u;
  RW(m13) RW(m15) RS(26) RS(6)
  x0 += k1; x1 += k2 + 3u;
  RW(m17) RW(m29) RS(16) RS(24)
  x0 += k2; x1 += k3 + 4u;
  RW(m13) RW(m15) RS(26) RS(6)
  x0 += k3; x1 += k1 + 5u;
  return x0 ^ x1;
}

__device__ uint32_t tf_plain(uint32_t ctr, uint32_t k1, uint32_t k2, uint32_t k3) {
  uint32_t x0 = k1, x1 = ctr + k2;
  RS(13) RS(15) RS(26) RS(6)
  x0 += k2; x1 += k3 + 1u;
  RS(17) RS(29) RS(16) RS(24)
  x0 += k3; x1 += k1 + 2u;
  RS(13) RS(15) RS(26) RS(6)
  x0 += k1; x1 += k2 + 3u;
  RS(17) RS(29) RS(16) RS(24)
  x0 += k2; x1 += k3 + 4u;
  RS(13) RS(15) RS(26) RS(6)
  x0 += k3; x1 += k1 + 5u;
  return x0 ^ x1;
}

static void host_threefry(uint32_t k1, uint32_t k2, uint32_t& x0, uint32_t& x1) {
  uint32_t k3 = k1 ^ k2 ^ 0x1BD11BDAu;
  x0 += k1; x1 += k2;
#define TFRH(r) { x0 += x1; x1 = (x1 << (r)) | (x1 >> (32 - (r))); x1 ^= x0; }
  TFRH(13) TFRH(15) TFRH(26) TFRH(6)
  x0 += k2; x1 += k3 + 1u;
  TFRH(17) TFRH(29) TFRH(16) TFRH(24)
  x0 += k3; x1 += k1 + 2u;
  TFRH(13) TFRH(15) TFRH(26) TFRH(6)
  x0 += k1; x1 += k2 + 3u;
  TFRH(17) TFRH(29) TFRH(16) TFRH(24)
  x0 += k2; x1 += k3 + 4u;
  TFRH(13) TFRH(15) TFRH(26) TFRH(6)
  x0 += k3; x1 += k1 + 5u;
#undef TFRH
}

__device__ __forceinline__ float sigmoidf_(float x) {
  if (x >= 0.f) { float z = expf(-x); return 1.f / (1.f + z); }
  float z = expf(x); return z / (1.f + z);
}

// Exact reference value for one element, byte-identical to the validated
// Round-4 pipeline:  v = log(p + 1e-9) + (-log(-log(max(tiny, f)))).
// __noinline__ keeps the rare refine path out of the hot loop's I-footprint.
__device__ __noinline__ float refine_v(uint32_t ctr, float pj,
                                       uint32_t k1, uint32_t k2, uint32_t k3) {
  uint32_t bits = tf_plain(ctr, k1, k2, k3);
  float f = __uint_as_float((bits >> 9) | 0x3f800000u) - 1.0f;
  float u = fmaxf(1.17549435e-38f, f);
  float g = -logf(-logf(u));
  return logf(pj + 1e-9f) + g;
}

__global__ void init_walk_kernel() {
  int p = blockIdx.x * 256 + threadIdx.x;
  if (p < NPAIR) g_walk[0][p] = p & (NN - 1);
}

// ---------------------------------------------------------------------------
// One Gumbel-max categorical step via the exponential-race identity:
//   argmax_j (log p_j + g_j)  ==  argmin_j (-log u_j) / p_j
// Pass 1: cheap bounded surrogate r~ (no logf). r~/r in [0.74, 1.51].
// Pass 2: exact float re-evaluation of candidates r~ <= 6 * min(r~)
//         (required margin 2.04 -> 3x safety), exact argmax + tie rule.
// ---------------------------------------------------------------------------
__global__ void __launch_bounds__(256) walk_step_kernel(
    int t, uint32_t k1, uint32_t k2, const float* __restrict__ prob) {
  __shared__ float sv[8];
  __shared__ int   sj[8];

  const uint32_t k3  = k1 ^ k2 ^ 0x1BD11BDAu;
  const uint32_t m13 = g_rotm[0], m15 = g_rotm[1];
  const uint32_t m17 = g_rotm[2], m29 = g_rotm[3];

  int p   = blockIdx.x;                    // r*N + n
  int tid = threadIdx.x;
  int cur = g_walk[t - 1][p];
  const float*  row  = prob + (size_t)cur * NN;
  const float4* prow = reinterpret_cast<const float4*>(row);
  uint32_t base = (uint32_t)p * (uint32_t)NN;

  float rt[16];
  float rmin = 3.4e38f;
#pragma unroll
  for (int g4 = 0; g4 < 4; g4++) {
    int q = g4 * 256 + tid;
    float4 pv = __ldg(prow + q);
    uint32_t c0 = base + ((uint32_t)q << 2);
    float pe[4] = {pv.x, pv.y, pv.z, pv.w};
#pragma unroll
    for (int c = 0; c < 4; c++) {
      uint32_t bits = tf_wide(c0 + (uint32_t)c, k1, k2, k3, m13, m15, m17, m29);
      float f = __uint_as_float((bits >> 9) | 0x3f800000u) - 1.0f;
      float u = fmaxf(1.17549435e-38f, f);
      // cheap bounded estimate of w = -log(u)
      float e  = 1.0f - u;                                     // exact for u>=0.5
      float wa = e * fmaf(e, fmaf(e, 0.33333334f, 0.5f), 1.0f); // series, ratio [0.96,1]
      float Bf = (float)(__float_as_uint(u) >> 23);
      float wb = fmaf(Bf, -0.69314718f, 87.683136f);            // exponent est, ratio [0.75,1.5]
      float w  = (u >= 0.5f) ? wa : wb;
      float rp; asm("rcp.approx.f32 %0, %1;" : "=f"(rp) : "f"(pe[c]));
      float r = w * rp;
      rt[g4 * 4 + c] = r;
      rmin = fminf(rmin, r);
    }
  }

  // block-wide min of the surrogate
  for (int off = 16; off; off >>= 1)
    rmin = fminf(rmin, __shfl_xor_sync(0xffffffffu, rmin, off));
  if ((tid & 31) == 0) sv[tid >> 5] = rmin;
  __syncthreads();
  float bm = sv[0];
#pragma unroll
  for (int i = 1; i < 8; i++) bm = fminf(bm, sv[i]);
  float thr = 6.0f * bm;

  // Pass 2: exact evaluation of candidates only
  float bv = __int_as_float(0xff800000);   // -inf
  int   bj = 0;
#pragma unroll
  for (int i = 0; i < 16; i++) {
    if (rt[i] <= thr) {
      int q = (i >> 2) * 256 + tid;
      int j = (q << 2) + (i & 3);
      float v = refine_v(base + (uint32_t)j, __ldg(row + j), k1, k2, k3);
      if (v > bv || (v == bv && j < bj)) { bv = v; bj = j; }
    }
  }

  // exact argmax reduction (first index on ties)
  for (int off = 16; off; off >>= 1) {
    float ov = __shfl_down_sync(0xffffffffu, bv, off);
    int   oj = __shfl_down_sync(0xffffffffu, bj, off);
    if (ov > bv || (ov == bv && oj < bj)) { bv = ov; bj = oj; }
  }
  __syncthreads();                          // done reading sv before overwrite
  if ((tid & 31) == 0) { sv[tid >> 5] = bv; sj[tid >> 5] = bj; }
  __syncthreads();
  if (tid == 0) {
    bv = sv[0]; bj = sj[0];
    for (int w2 = 1; w2 < 8; w2++)
      if (sv[w2] > bv || (sv[w2] == bv && sj[w2] < bj)) { bv = sv[w2]; bj = sj[w2]; }
    g_walk[t][p] = bj;
  }
}

// ---------------------------------------------------------------------------
// Trajectory recurrence. One warp per (r,n); 8 warps per block. Full fp32.
// ---------------------------------------------------------------------------
__global__ void __launch_bounds__(256) rye_kernel(
    const float* __restrict__ inv_in, const float* __restrict__ eq_in,
    const float* __restrict__ W1, const float* __restrict__ b1,
    const float* __restrict__ W2, const float* __restrict__ b2,
    float* __restrict__ out) {
  __shared__ float sW1[FEAT * HH];       // 36864 B
  __shared__ float sW2[HH * 2 * CC];     // 8192 B
  __shared__ float sb1[HH];
  __shared__ float sb2[2 * CC];
  __shared__ float sfeat[8][FEAT];       // features per warp
  __shared__ float seqh[8][3 * CC];      // eq hidden state
  __shared__ float scoef[8][2 * CC];
  __shared__ float seqin[8][4];          // eq_diff (3 used)

  int tid = threadIdx.x;
  for (int i = tid; i < FEAT * HH; i += 256) sW1[i] = W1[i];
  for (int i = tid; i < HH * 2 * CC; i += 256) sW2[i] = W2[i];
  if (tid < HH)     sb1[tid] = b1[tid];
  if (tid < 2 * CC) sb2[tid] = b2[tid];

  int w    = tid >> 5;
  int lane = tid & 31;
  int pair = blockIdx.x * 8 + w;
  int r    = pair >> 12;
  int n    = pair & (NN - 1);

  sfeat[w][FF + lane]      = 0.f;
  sfeat[w][FF + 32 + lane] = 0.f;
  if (lane < 16) {
    seqh[w][lane] = 0.f; seqh[w][16 + lane] = 0.f; seqh[w][32 + lane] = 0.f;
  }
  __syncthreads();

  const size_t EQ_BASE = (size_t)RR * LL * NN * HH;   // 8388608

  for (int l = 0; l < LL; l++) {
    int node = g_walk[LL - 1 - l][pair];
    sfeat[w][lane]      = __ldg(inv_in + (size_t)node * FF + lane);
    sfeat[w][32 + lane] = __ldg(inv_in + (size_t)node * FF + 32 + lane);
    if (lane < 3) {
      float e = 0.f;
      if (l > 0) {
        int prev = g_walk[LL - l][pair];
        e = __ldg(eq_in + (size_t)node * 3 + lane) - __ldg(eq_in + (size_t)prev * 3 + lane);
      }
      seqin[w][lane] = e;
    }
    if (lane < 16) {
      float d0 = seqh[w][lane], d1 = seqh[w][16 + lane], d2 = seqh[w][32 + lane];
      sfeat[w][FF + HH + lane] = d0 * d0 + d1 * d1 + d2 * d2;
    }
    __syncwarp();

    // GEMV1: inv_h_new = tanh(feats @ W1 + b1); lane does h=lane, h+32
    float a0 = 0.f, a1 = 0.f;
#pragma unroll 4
    for (int k = 0; k < FEAT; k++) {
      float fk = sfeat[w][k];
      a0 = fmaf(fk, sW1[k * HH + lane], a0);
      a1 = fmaf(fk, sW1[k * HH + 32 + lane], a1);
    }
    float h0 = tanhf(a0 + sb1[lane]);
    float h1 = tanhf(a1 + sb1[32 + lane]);
    __syncwarp();
    sfeat[w][FF + lane]      = h0;
    sfeat[w][FF + 32 + lane] = h1;
    __syncwarp();

    // GEMV2: coef = inv_h_new @ W2 + b2
    float acc = 0.f;
#pragma unroll 8
    for (int k = 0; k < HH; k++)
      acc = fmaf(sfeat[w][FF + k], sW2[k * (2 * CC) + lane], acc);
    scoef[w][lane] = acc + sb2[lane];
    __syncwarp();

    size_t inv_off = (((size_t)r * LL + l) * NN + n) * HH;
    out[inv_off + lane]      = h0;
    out[inv_off + 32 + lane] = h1;
    if (lane < 16) {
      float gate = sigmoidf_(scoef[w][lane]);
      float scl  = scoef[w][CC + lane];
      size_t eq_off = EQ_BASE + (((size_t)r * LL + l) * NN + n) * (3 * CC) + lane;
      float e0 = seqin[w][0], e1 = seqin[w][1], e2 = seqin[w][2];
      float v0 = seqh[w][lane]      * gate + e0 * scl;
      float v1 = seqh[w][16 + lane] * gate + e1 * scl;
      float v2 = seqh[w][32 + lane] * gate + e2 * scl;
      seqh[w][lane] = v0; seqh[w][16 + lane] = v1; seqh[w][32 + lane] = v2;
      out[eq_off]           = v0;
      out[eq_off + CC]      = v1;
      out[eq_off + 2 * CC]  = v2;
    }
    __syncwarp();
  }
}

// ---------------------------------------------------------------------------
extern "C" void kernel_launch(void* const* d_in, const int* in_sizes, int n_in,
                              void* d_out, int out_size) {
  const float* prob = (const float*)d_in[0];
  const float* inv  = (const float*)d_in[1];
  const float* eq   = (const float*)d_in[2];
  const float* W1   = (const float*)d_in[3];
  const float* b1   = (const float*)d_in[4];
  const float* W2   = (const float*)d_in[5];
  const float* b2   = (const float*)d_in[6];
  float* out = (float*)d_out;
  (void)in_sizes; (void)n_in; (void)out_size;

  init_walk_kernel<<<NPAIR / 256, 256>>>();

  // Step keys: subkey[t] = threefry2x32((0,42), (0, t))
  for (int t = 1; t < LL; t++) {
    uint32_t x0 = 0u, x1 = (uint32_t)(t - 1);
    host_threefry(0u, 42u, x0, x1);
    walk_step_kernel<<<NPAIR, 256>>>(t, x0, x1, prob);
  }

  rye_kernel<<<NPAIR / 8, 256>>>(inv, eq, W1, b1, W2, b2, out);
}

// round 6
// speedup vs baseline: 1.2691x; 1.1934x over previous
#include <cuda_runtime.h>
#include <cstdint>

// Problem constants
#define NN    4096
#define RR    4
#define LL    8
#define HH    64
#define CC    16
#define FF    64
#define FEAT  144            // FF + HH + CC
#define NPAIR (RR*NN)        // 16384

// Candidate filter: bits >= B0  <=>  (bits>>9) >= 8360588  <=>  g >= ~5.6999
// Excluded elements provably have v = lg + g < 5.69994 + 0.0011 < VSAFE.
#define B0_BITS 4280621056u          // 8360588u << 9
#define VSAFE   5.705f

// Device scratch (static data: no runtime allocation)
__device__ int      g_walk[LL][NPAIR];    // un-flipped walk nodes: [t][r*N+n]
__device__ uint32_t g_rotm[4] = {1u << 13, 1u << 15, 1u << 17, 1u << 29};

struct Keys { uint32_t k1[LL], k2[LL]; };

// ---------------------------------------------------------------------------
// Threefry-2x32, 20 rounds — canonical, matches JAX's threefry2x32 primitive.
// RS: shift-form rotation (SHF, ALU pipe).
// RW: wide-multiply rotation (IMAD.WIDE, FMA pipe) — multiplier from a runtime
//     register so ptxas cannot strength-reduce it back to shifts.
// ---------------------------------------------------------------------------
#define RS(r) { x0 += x1; x1 = __funnelshift_l(x1, x1, (r)) ^ x0; }
#define RW(m) { x0 += x1; unsigned long long tt = (unsigned long long)x1 * (m); \
                x1 = ((uint32_t)tt | (uint32_t)(tt >> 32)) ^ x0; }

__device__ __forceinline__ uint32_t tf_wide(uint32_t ctr,
                                            uint32_t k1, uint32_t k2, uint32_t k3,
                                            uint32_t m13, uint32_t m15,
                                            uint32_t m17, uint32_t m29) {
  uint32_t x0 = k1, x1 = ctr + k2;
  RW(m13) RW(m15) RS(26) RS(6)
  x0 += k2; x1 += k3 + 1u;
  RW(m17) RW(m29) RS(16) RS(24)
  x0 += k3; x1 += k1 + 2u;
  RW(m13) RW(m15) RS(26) RS(6)
  x0 += k1; x1 += k2 + 3u;
  RW(m17) RW(m29) RS(16) RS(24)
  x0 += k2; x1 += k3 + 4u;
  RW(m13) RW(m15) RS(26) RS(6)
  x0 += k3; x1 += k1 + 5u;
  return x0 ^ x1;
}

__device__ uint32_t tf_plain(uint32_t ctr, uint32_t k1, uint32_t k2, uint32_t k3) {
  uint32_t x0 = k1, x1 = ctr + k2;
  RS(13) RS(15) RS(26) RS(6)
  x0 += k2; x1 += k3 + 1u;
  RS(17) RS(29) RS(16) RS(24)
  x0 += k3; x1 += k1 + 2u;
  RS(13) RS(15) RS(26) RS(6)
  x0 += k1; x1 += k2 + 3u;
  RS(17) RS(29) RS(16) RS(24)
  x0 += k2; x1 += k3 + 4u;
  RS(13) RS(15) RS(26) RS(6)
  x0 += k3; x1 += k1 + 5u;
  return x0 ^ x1;
}

static void host_threefry(uint32_t k1, uint32_t k2, uint32_t& x0, uint32_t& x1) {
  uint32_t k3 = k1 ^ k2 ^ 0x1BD11BDAu;
  x0 += k1; x1 += k2;
#define TFRH(r) { x0 += x1; x1 = (x1 << (r)) | (x1 >> (32 - (r))); x1 ^= x0; }
  TFRH(13) TFRH(15) TFRH(26) TFRH(6)
  x0 += k2; x1 += k3 + 1u;
  TFRH(17) TFRH(29) TFRH(16) TFRH(24)
  x0 += k3; x1 += k1 + 2u;
  TFRH(13) TFRH(15) TFRH(26) TFRH(6)
  x0 += k1; x1 += k2 + 3u;
  TFRH(17) TFRH(29) TFRH(16) TFRH(24)
  x0 += k2; x1 += k3 + 4u;
  TFRH(13) TFRH(15) TFRH(26) TFRH(6)
  x0 += k3; x1 += k1 + 5u;
#undef TFRH
}

__device__ __forceinline__ float sigmoidf_(float x) {
  if (x >= 0.f) { float z = expf(-x); return 1.f / (1.f + z); }
  float z = expf(x); return z / (1.f + z);
}

// Exact reference value, byte-identical to the validated pipeline:
//   v = log(p + 1e-9) + (-log(-log(max(tiny, f))))
__device__ __noinline__ float refine_v(uint32_t ctr, float pj,
                                       uint32_t k1, uint32_t k2, uint32_t k3) {
  uint32_t bits = tf_plain(ctr, k1, k2, k3);
  float f = __uint_as_float((bits >> 9) | 0x3f800000u) - 1.0f;
  float u = fmaxf(1.17549435e-38f, f);
  float g = -logf(-logf(u));
  return logf(pj + 1e-9f) + g;
}

// Block-wide argmax with first-index tie rule. Leaves result in *s_bv/*s_bj.
__device__ __forceinline__ void block_argmax(float bv, int bj, int tid,
                                             float* sv, int* sj,
                                             float* s_bv, int* s_bj) {
  for (int off = 16; off; off >>= 1) {
    float ov = __shfl_down_sync(0xffffffffu, bv, off);
    int   oj = __shfl_down_sync(0xffffffffu, bj, off);
    if (ov > bv || (ov == bv && oj < bj)) { bv = ov; bj = oj; }
  }
  __syncthreads();                        // protect sv/sj reuse across calls
  if ((tid & 31) == 0) { sv[tid >> 5] = bv; sj[tid >> 5] = bj; }
  __syncthreads();
  if (tid == 0) {
    float xb = sv[0]; int xj = sj[0];
    for (int w = 1; w < 8; w++)
      if (sv[w] > xb || (sv[w] == xb && sj[w] < xj)) { xb = sv[w]; xj = sj[w]; }
    *s_bv = xb; *s_bj = xj;
  }
  __syncthreads();
}

// ---------------------------------------------------------------------------
// Fused walk kernel: one block per (r,n) pair runs all 7 Gumbel-max steps.
// Pass 1 per step: Threefry + integer compare only (no loads, no float math).
// Candidates compacted into shared; exact refine on <=64 of them; provable
// safety bound, else exact full-row fallback (bit-identical result).
// ---------------------------------------------------------------------------
__global__ void __launch_bounds__(256, 8) walk_all_kernel(
    const float* __restrict__ prob, Keys ks) {
  __shared__ float sv[8];
  __shared__ int   sj[8];
  __shared__ float s_bv;
  __shared__ int   s_bj;
  __shared__ int   s_cnt;
  __shared__ int   s_cand[64];

  const uint32_t m13 = g_rotm[0], m15 = g_rotm[1];
  const uint32_t m17 = g_rotm[2], m29 = g_rotm[3];

  int p   = blockIdx.x;                  // r*N + n
  int tid = threadIdx.x;
  uint32_t base = (uint32_t)p << 12;     // p * NN
  int cur = p & (NN - 1);
  if (tid == 0) g_walk[0][p] = cur;

  for (int t = 1; t < LL; t++) {
    uint32_t k1 = ks.k1[t], k2 = ks.k2[t];
    uint32_t k3 = k1 ^ k2 ^ 0x1BD11BDAu;
    const float* __restrict__ row = prob + (size_t)cur * NN;

    if (tid == 0) s_cnt = 0;
    __syncthreads();

    // Pass 1: Threefry + integer threshold. Candidate rate ~0.33%.
    uint32_t c0 = base + (uint32_t)tid;
#pragma unroll
    for (int g = 0; g < NN / 256; g++) {
      uint32_t bits = tf_wide(c0 + (uint32_t)(g * 256), k1, k2, k3,
                              m13, m15, m17, m29);
      if (bits >= B0_BITS) {
        int slot = atomicAdd(&s_cnt, 1);
        if (slot < 64) s_cand[slot] = g * 256 + tid;
      }
    }
    __syncthreads();

    // Pass 2: exact evaluation of the compacted candidates.
    int   ncand = s_cnt;
    float bv = __int_as_float(0xff800000);   // -inf
    int   bj = 0x7fffffff;
    if (tid < ncand && tid < 64) {
      int j = s_cand[tid];
      bv = refine_v(base + (uint32_t)j, __ldg(row + j), k1, k2, k3);
      bj = j;
    }
    block_argmax(bv, bj, tid, sv, sj, &s_bv, &s_bj);

    // Safety: excluded elements are provably < VSAFE. Overflow or low max
    // -> exact full-row scan (rare: ~0.1% of rows).
    if (ncand > 64 || !(s_bv >= VSAFE)) {
      bv = __int_as_float(0xff800000);
      bj = 0x7fffffff;
#pragma unroll 4
      for (int g = 0; g < NN / 256; g++) {
        int j = g * 256 + tid;
        float v = refine_v(base + (uint32_t)j, __ldg(row + j), k1, k2, k3);
        if (v > bv || (v == bv && j < bj)) { bv = v; bj = j; }
      }
      block_argmax(bv, bj, tid, sv, sj, &s_bv, &s_bj);
    }

    cur = s_bj;
    if (tid == 0) g_walk[t][p] = cur;
    __syncthreads();
  }
}

// ---------------------------------------------------------------------------
// Trajectory recurrence. One warp per (r,n); 8 warps per block. Full fp32.
// ---------------------------------------------------------------------------
__global__ void __launch_bounds__(256) rye_kernel(
    const float* __restrict__ inv_in, const float* __restrict__ eq_in,
    const float* __restrict__ W1, const float* __restrict__ b1,
    const float* __restrict__ W2, const float* __restrict__ b2,
    float* __restrict__ out) {
  __shared__ float sW1[FEAT * HH];       // 36864 B
  __shared__ float sW2[HH * 2 * CC];     // 8192 B
  __shared__ float sb1[HH];
  __shared__ float sb2[2 * CC];
  __shared__ float sfeat[8][FEAT];       // features per warp
  __shared__ float seqh[8][3 * CC];      // eq hidden state
  __shared__ float scoef[8][2 * CC];
  __shared__ float seqin[8][4];          // eq_diff (3 used)

  int tid = threadIdx.x;
  for (int i = tid; i < FEAT * HH; i += 256) sW1[i] = W1[i];
  for (int i = tid; i < HH * 2 * CC; i += 256) sW2[i] = W2[i];
  if (tid < HH)     sb1[tid] = b1[tid];
  if (tid < 2 * CC) sb2[tid] = b2[tid];

  int w    = tid >> 5;
  int lane = tid & 31;
  int pair = blockIdx.x * 8 + w;
  int r    = pair >> 12;
  int n    = pair & (NN - 1);

  sfeat[w][FF + lane]      = 0.f;
  sfeat[w][FF + 32 + lane] = 0.f;
  if (lane < 16) {
    seqh[w][lane] = 0.f; seqh[w][16 + lane] = 0.f; seqh[w][32 + lane] = 0.f;
  }
  __syncthreads();

  const size_t EQ_BASE = (size_t)RR * LL * NN * HH;   // 8388608

  for (int l = 0; l < LL; l++) {
    int node = g_walk[LL - 1 - l][pair];
    sfeat[w][lane]      = __ldg(inv_in + (size_t)node * FF + lane);
    sfeat[w][32 + lane] = __ldg(inv_in + (size_t)node * FF + 32 + lane);
    if (lane < 3) {
      float e = 0.f;
      if (l > 0) {
        int prev = g_walk[LL - l][pair];
        e = __ldg(eq_in + (size_t)node * 3 + lane) - __ldg(eq_in + (size_t)prev * 3 + lane);
      }
      seqin[w][lane] = e;
    }
    if (lane < 16) {
      float d0 = seqh[w][lane], d1 = seqh[w][16 + lane], d2 = seqh[w][32 + lane];
      sfeat[w][FF + HH + lane] = d0 * d0 + d1 * d1 + d2 * d2;
    }
    __syncwarp();

    // GEMV1: inv_h_new = tanh(feats @ W1 + b1); lane does h=lane, h+32
    float a0 = 0.f, a1 = 0.f;
#pragma unroll 4
    for (int k = 0; k < FEAT; k++) {
      float fk = sfeat[w][k];
      a0 = fmaf(fk, sW1[k * HH + lane], a0);
      a1 = fmaf(fk, sW1[k * HH + 32 + lane], a1);
    }
    float h0 = tanhf(a0 + sb1[lane]);
    float h1 = tanhf(a1 + sb1[32 + lane]);
    __syncwarp();
    sfeat[w][FF + lane]      = h0;
    sfeat[w][FF + 32 + lane] = h1;
    __syncwarp();

    // GEMV2: coef = inv_h_new @ W2 + b2
    float acc = 0.f;
#pragma unroll 8
    for (int k = 0; k < HH; k++)
      acc = fmaf(sfeat[w][FF + k], sW2[k * (2 * CC) + lane], acc);
    scoef[w][lane] = acc + sb2[lane];
    __syncwarp();

    size_t inv_off = (((size_t)r * LL + l) * NN + n) * HH;
    out[inv_off + lane]      = h0;
    out[inv_off + 32 + lane] = h1;
    if (lane < 16) {
      float gate = sigmoidf_(scoef[w][lane]);
      float scl  = scoef[w][CC + lane];
      size_t eq_off = EQ_BASE + (((size_t)r * LL + l) * NN + n) * (3 * CC) + lane;
      float e0 = seqin[w][0], e1 = seqin[w][1], e2 = seqin[w][2];
      float v0 = seqh[w][lane]      * gate + e0 * scl;
      float v1 = seqh[w][16 + lane] * gate + e1 * scl;
      float v2 = seqh[w][32 + lane] * gate + e2 * scl;
      seqh[w][lane] = v0; seqh[w][16 + lane] = v1; seqh[w][32 + lane] = v2;
      out[eq_off]           = v0;
      out[eq_off + CC]      = v1;
      out[eq_off + 2 * CC]  = v2;
    }
    __syncwarp();
  }
}

// ---------------------------------------------------------------------------
extern "C" void kernel_launch(void* const* d_in, const int* in_sizes, int n_in,
                              void* d_out, int out_size) {
  const float* prob = (const float*)d_in[0];
  const float* inv  = (const float*)d_in[1];
  const float* eq   = (const float*)d_in[2];
  const float* W1   = (const float*)d_in[3];
  const float* b1   = (const float*)d_in[4];
  const float* W2   = (const float*)d_in[5];
  const float* b2   = (const float*)d_in[6];
  float* out = (float*)d_out;
  (void)in_sizes; (void)n_in; (void)out_size;

  // Step keys: subkey[t] = threefry2x32((0,42), (0, t-1))
  Keys ks;
  for (int t = 1; t < LL; t++) {
    uint32_t x0 = 0u, x1 = (uint32_t)(t - 1);
    host_threefry(0u, 42u, x0, x1);
    ks.k1[t] = x0; ks.k2[t] = x1;
  }
  ks.k1[0] = 0; ks.k2[0] = 0;

  walk_all_kernel<<<NPAIR, 256>>>(prob, ks);
  rye_kernel<<<NPAIR / 8, 256>>>(inv, eq, W1, b1, W2, b2, out);
}